// round 2
// baseline (speedup 1.0000x reference)
#include <cuda_runtime.h>
#include <math.h>

#define Bz 32
#define Tz 128
#define Vz 16000
#define Ez 512
#define Hz 1024
#define Fz 2048

// -------- scratch (static device globals; no runtime allocation) --------
__device__ float g_pooled[Bz * Fz];          // 256 KB
__device__ float g_h0[Bz * Hz];
__device__ float g_h1[Bz * Hz];
__device__ float g_c[Bz * Hz];
__device__ float g_xW[Bz * Tz * 4 * Hz];     // 64 MB : per-(b,t) input-gate preactivations
__device__ float g_hs[Bz * Tz * Hz];         // 16 MB : all hidden states
__device__ int   g_idx[Bz * Tz];

__device__ __forceinline__ float sigmoidf_(float x) {
    return 1.0f / (1.0f + expf(-x));
}

// -------- stage 1: 7x7 average pool --------
__global__ void pool_kernel(const float* __restrict__ features) {
    int n = blockIdx.x * blockDim.x + threadIdx.x;   // Bz*Fz = 65536
    if (n >= Bz * Fz) return;
    const float* p = features + (size_t)n * 49;
    float s = 0.f;
#pragma unroll
    for (int i = 0; i < 49; i++) s += p[i];
    g_pooled[n] = s * (1.0f / 49.0f);
}

// -------- stage 1b: shifted input token indices --------
__global__ void idx_kernel(const int* __restrict__ reports) {
    int n = blockIdx.x * blockDim.x + threadIdx.x;   // Bz*Tz = 4096
    if (n >= Bz * Tz) return;
    int t = n & (Tz - 1);
    g_idx[n] = (t == 0) ? 1 : reports[n - 1];        // START_IDX = 1
}

// -------- stage 2: init = pooled @ fc_W^T + fc_b  ->  h0, c0 --------
__global__ void init_kernel(const float* __restrict__ fc_W, const float* __restrict__ fc_b) {
    __shared__ float sp[Fz];
    int b = blockIdx.x;
    int tid = threadIdx.x;
    for (int i = tid; i < Fz; i += 256) sp[i] = g_pooled[b * Fz + i];
    __syncthreads();
    for (int j = tid; j < 2 * Hz; j += 256) {
        const float* wrow = fc_W + (size_t)j * Fz;
        float acc = fc_b[j];
#pragma unroll 8
        for (int f = 0; f < Fz; f++) acc += sp[f] * wrow[f];
        if (j < Hz) g_h0[b * Hz + j] = acc;
        else        g_c[b * Hz + (j - Hz)] = acc;
    }
}

// -------- generic fp32 GEMM: C[M,N] = A[M,K] @ Bmat[N,K]^T + bias (+bias2) --------
// mode 0: A rows gathered from emb via g_idx, C = g_xW      (M=4096, N=4096, K=512)
// mode 1: A = g_hs, C = Cext (the output tensor)            (M=4096, N=16000, K=1024)
// All of M, N divisible by 128; K divisible by 8.
__global__ __launch_bounds__(256)
void sgemm_kernel(const float* __restrict__ Aext, const float* __restrict__ Bmat,
                  const float* __restrict__ bias, const float* __restrict__ bias2,
                  float* __restrict__ Cext, int N, int K, int mode)
{
    __shared__ float As[8][128];
    __shared__ float Bs[8][128];

    const float* A = (mode == 0) ? Aext : g_hs;
    float* C = (mode == 0) ? g_xW : Cext;

    int tid = threadIdx.x;
    int m0 = blockIdx.y * 128;
    int n0 = blockIdx.x * 128;

    int ldRow = tid >> 1;          // 0..127
    int ldK   = (tid & 1) * 4;     // 0 or 4

    const float* aBase;
    if (mode == 0) aBase = Aext + (size_t)g_idx[m0 + ldRow] * K;
    else           aBase = A + (size_t)(m0 + ldRow) * K;
    const float* bBase = Bmat + (size_t)(n0 + ldRow) * K;

    int ty = tid >> 4;             // 0..15
    int tx = tid & 15;             // 0..15

    float acc[8][8];
#pragma unroll
    for (int i = 0; i < 8; i++)
#pragma unroll
        for (int j = 0; j < 8; j++) acc[i][j] = 0.f;

    for (int k0 = 0; k0 < K; k0 += 8) {
        float4 av = *(const float4*)(aBase + k0 + ldK);
        float4 bv = *(const float4*)(bBase + k0 + ldK);
        As[ldK + 0][ldRow] = av.x; As[ldK + 1][ldRow] = av.y;
        As[ldK + 2][ldRow] = av.z; As[ldK + 3][ldRow] = av.w;
        Bs[ldK + 0][ldRow] = bv.x; Bs[ldK + 1][ldRow] = bv.y;
        Bs[ldK + 2][ldRow] = bv.z; Bs[ldK + 3][ldRow] = bv.w;
        __syncthreads();
#pragma unroll
        for (int kk = 0; kk < 8; kk++) {
            float ar[8], br[8];
#pragma unroll
            for (int i = 0; i < 8; i++) ar[i] = As[kk][ty * 8 + i];
#pragma unroll
            for (int j = 0; j < 8; j++) br[j] = Bs[kk][tx * 8 + j];
#pragma unroll
            for (int i = 0; i < 8; i++)
#pragma unroll
                for (int j = 0; j < 8; j++) acc[i][j] += ar[i] * br[j];
        }
        __syncthreads();
    }

#pragma unroll
    for (int i = 0; i < 8; i++) {
        int m = m0 + ty * 8 + i;
        float* crow = C + (size_t)m * N + n0 + tx * 8;
#pragma unroll
        for (int j = 0; j < 8; j++) {
            int n = n0 + tx * 8 + j;
            float v = acc[i][j] + bias[n];
            if (bias2) v += bias2[n];
            crow[j] = v;
        }
    }
}

// -------- stage 3: one LSTM step (launched 128x, serialized by stream order) --------
// grid = 128 blocks; block bx owns j in [bx*8, bx*8+8) across ALL 4 gates and ALL 32 b.
// Reads h_in (parity buffer), writes h_out + g_c (block-private slice) + g_hs.
__global__ __launch_bounds__(256)
void lstm_step_kernel(const float* __restrict__ Whh, int t, int parity)
{
    __shared__ float ht[32][64];     // h tile   [b][k]
    __shared__ float wt[32][65];     // Whh tile [gate-row][k], padded
    __shared__ float gs[32][33];     // gate sums [b][r], padded

    const float* h_in  = parity ? g_h1 : g_h0;
    float*       h_out = parity ? g_h0 : g_h1;

    int tid = threadIdx.x;
    int j0 = blockIdx.x * 8;
    int rr = tid & 31;               // which of the 32 gate-rows
    int b0 = (tid >> 5) * 4;         // this thread handles b0..b0+3
    // gate-row rr -> global row q*Hz + j0 + jj  where q=rr/8, jj=rr%8
    float acc0 = 0.f, acc1 = 0.f, acc2 = 0.f, acc3 = 0.f;

    for (int k0 = 0; k0 < Hz; k0 += 64) {
        for (int i = tid; i < 32 * 64; i += 256) {
            int b = i >> 6, k = i & 63;
            ht[b][k] = h_in[b * Hz + k0 + k];
        }
        for (int i = tid; i < 32 * 64; i += 256) {
            int r = i >> 6, k = i & 63;
            int grow = (r >> 3) * Hz + j0 + (r & 7);
            wt[r][k] = Whh[(size_t)grow * Hz + k0 + k];
        }
        __syncthreads();
#pragma unroll 8
        for (int k = 0; k < 64; k++) {
            float w = wt[rr][k];
            acc0 += ht[b0 + 0][k] * w;
            acc1 += ht[b0 + 1][k] * w;
            acc2 += ht[b0 + 2][k] * w;
            acc3 += ht[b0 + 3][k] * w;
        }
        __syncthreads();
    }

    gs[b0 + 0][rr] = acc0;
    gs[b0 + 1][rr] = acc1;
    gs[b0 + 2][rr] = acc2;
    gs[b0 + 3][rr] = acc3;
    __syncthreads();

    // elementwise: 256 threads = 32 b x 8 jj
    int b = tid >> 3;
    int jj = tid & 7;
    size_t gbase = ((size_t)b * Tz + t) * (4 * Hz);
    float gi = gs[b][ 0 + jj] + g_xW[gbase + 0 * Hz + j0 + jj];
    float gf = gs[b][ 8 + jj] + g_xW[gbase + 1 * Hz + j0 + jj];
    float gg = gs[b][16 + jj] + g_xW[gbase + 2 * Hz + j0 + jj];
    float go = gs[b][24 + jj] + g_xW[gbase + 3 * Hz + j0 + jj];

    int hidx = b * Hz + j0 + jj;
    float cold = g_c[hidx];
    float cn = sigmoidf_(gf) * cold + sigmoidf_(gi) * tanhf(gg);
    float hn = sigmoidf_(go) * tanhf(cn);
    g_c[hidx] = cn;
    h_out[hidx] = hn;
    g_hs[((size_t)b * Tz + t) * Hz + j0 + jj] = hn;
}

// -------- combined bias (b_ih + b_hh) is folded via bias2 in sgemm --------

extern "C" void kernel_launch(void* const* d_in, const int* in_sizes, int n_in,
                              void* d_out, int out_size) {
    const float* features = (const float*)d_in[0];
    const int*   reports  = (const int*)d_in[1];
    const float* fc_W     = (const float*)d_in[2];
    const float* fc_b     = (const float*)d_in[3];
    const float* emb      = (const float*)d_in[4];
    const float* W_ih     = (const float*)d_in[5];
    const float* W_hh     = (const float*)d_in[6];
    const float* b_ih     = (const float*)d_in[7];
    const float* b_hh     = (const float*)d_in[8];
    const float* Wv       = (const float*)d_in[9];
    const float* bv       = (const float*)d_in[10];
    float* out = (float*)d_out;

    (void)in_sizes; (void)n_in; (void)out_size;

    // stage 1: pool + indices
    pool_kernel<<<(Bz * Fz + 255) / 256, 256>>>(features);
    idx_kernel<<<(Bz * Tz + 255) / 256, 256>>>(reports);

    // stage 2: h0/c0 from fc
    init_kernel<<<Bz, 256>>>(fc_W, fc_b);

    // stage 2b: xW = emb[idx] @ W_ih^T + b_ih + b_hh   (M=4096, N=4096, K=512)
    {
        dim3 grid(4 * Hz / 128, Bz * Tz / 128);
        sgemm_kernel<<<grid, 256>>>(emb, W_ih, b_ih, b_hh, nullptr, 4 * Hz, Ez, 0);
    }

    // stage 3: 128 sequential LSTM steps
    for (int t = 0; t < Tz; t++) {
        lstm_step_kernel<<<Hz / 8, 256>>>(W_hh, t, t & 1);
    }

    // stage 4: out = hs @ Wv^T + bv   (M=4096, N=16000, K=1024)
    {
        dim3 grid(Vz / 128, Bz * Tz / 128);
        sgemm_kernel<<<grid, 256>>>(nullptr, Wv, bv, nullptr, out, Vz, Hz, 1);
    }
}

// round 3
// speedup vs baseline: 1.8643x; 1.8643x over previous
#include <cuda_runtime.h>
#include <math.h>
#include <stdint.h>

#define Bz 32
#define Tz 128
#define Vz 16000
#define Ez 512
#define Hz 1024
#define Fz 2048

// -------- scratch (static device globals; no runtime allocation) --------
__device__ float g_pooled[Bz * Fz];
__device__ float g_h0[Bz * Hz];
__device__ float g_h1[Bz * Hz];
__device__ float g_c[Bz * Hz];
__device__ float g_xW[Bz * Tz * 4 * Hz];     // 64 MB input-gate preactivations (fp32)
__device__ float g_hs[Bz * Tz * Hz];         // 16 MB hidden states, pre-rounded to tf32
__device__ float g_Wv[Vz * Hz];              // 64 MB Wv pre-rounded to tf32
__device__ int   g_idx[Bz * Tz];

__device__ __forceinline__ float sigmoidf_(float x) {
    return 1.0f / (1.0f + expf(-x));
}

__device__ __forceinline__ float round_tf32(float x) {
    uint32_t u;
    asm("cvt.rna.tf32.f32 %0, %1;" : "=r"(u) : "f"(x));
    return __uint_as_float(u);
}

__device__ __forceinline__ void cpasync16(void* dst, const void* src) {
    uint32_t d = (uint32_t)__cvta_generic_to_shared(dst);
    asm volatile("cp.async.cg.shared.global [%0], [%1], 16;" :: "r"(d), "l"(src));
}
__device__ __forceinline__ void cpasync_commit() {
    asm volatile("cp.async.commit_group;");
}
__device__ __forceinline__ void cpasync_wait0() {
    asm volatile("cp.async.wait_group 0;");
}

__device__ __forceinline__ void mma_tf32(float* c, const uint32_t* a, const uint32_t* b) {
    asm volatile(
        "mma.sync.aligned.m16n8k8.row.col.f32.tf32.tf32.f32 "
        "{%0,%1,%2,%3}, {%4,%5,%6,%7}, {%8,%9}, {%0,%1,%2,%3};"
        : "+f"(c[0]), "+f"(c[1]), "+f"(c[2]), "+f"(c[3])
        : "r"(a[0]), "r"(a[1]), "r"(a[2]), "r"(a[3]), "r"(b[0]), "r"(b[1]));
}

// -------- stage 1: 7x7 average pool --------
__global__ void pool_kernel(const float* __restrict__ features) {
    int n = blockIdx.x * blockDim.x + threadIdx.x;
    if (n >= Bz * Fz) return;
    const float* p = features + (size_t)n * 49;
    float s = 0.f;
#pragma unroll
    for (int i = 0; i < 49; i++) s += p[i];
    g_pooled[n] = s * (1.0f / 49.0f);
}

// -------- stage 1b: shifted input token indices --------
__global__ void idx_kernel(const int* __restrict__ reports) {
    int n = blockIdx.x * blockDim.x + threadIdx.x;
    if (n >= Bz * Tz) return;
    int t = n & (Tz - 1);
    g_idx[n] = (t == 0) ? 1 : reports[n - 1];        // START_IDX = 1
}

// -------- pre-round Wv to tf32 --------
__global__ void round_wv_kernel(const float* __restrict__ Wv) {
    int n = blockIdx.x * blockDim.x + threadIdx.x;
    if (n < Vz * Hz) g_Wv[n] = round_tf32(Wv[n]);
}

// -------- stage 2: init = pooled @ fc_W^T + fc_b  ->  h0, c0 (tiled, fp32) --------
// grid = 64 blocks, each owns 32 output rows (of 2048) x all 32 batches.
__global__ __launch_bounds__(256)
void init_kernel(const float* __restrict__ fc_W, const float* __restrict__ fc_b) {
    __shared__ float4 sp4[32][32];   // pooled [b][k4], chunk of 128 k
    __shared__ float4 wt4[32][33];   // fc_W  [row][k4], stride 33 -> conflict-free

    int tid = threadIdx.x;
    int r0 = blockIdx.x * 32;
    int rr = tid & 31;
    int b0 = (tid >> 5) * 4;
    float acc0 = 0.f, acc1 = 0.f, acc2 = 0.f, acc3 = 0.f;

    for (int k0 = 0; k0 < Fz; k0 += 128) {
        for (int i = tid; i < 32 * 32; i += 256) {
            int b = i >> 5, k4 = i & 31;
            sp4[b][k4] = *(const float4*)(g_pooled + b * Fz + k0 + 4 * k4);
        }
        for (int i = tid; i < 32 * 32; i += 256) {
            int r = i >> 5, k4 = i & 31;
            wt4[r][k4] = *(const float4*)(fc_W + (size_t)(r0 + r) * Fz + k0 + 4 * k4);
        }
        __syncthreads();
#pragma unroll 8
        for (int k4 = 0; k4 < 32; k4++) {
            float4 w = wt4[rr][k4];
            float4 p0 = sp4[b0 + 0][k4], p1 = sp4[b0 + 1][k4];
            float4 p2 = sp4[b0 + 2][k4], p3 = sp4[b0 + 3][k4];
            acc0 += w.x * p0.x + w.y * p0.y + w.z * p0.z + w.w * p0.w;
            acc1 += w.x * p1.x + w.y * p1.y + w.z * p1.z + w.w * p1.w;
            acc2 += w.x * p2.x + w.y * p2.y + w.z * p2.z + w.w * p2.w;
            acc3 += w.x * p3.x + w.y * p3.y + w.z * p3.z + w.w * p3.w;
        }
        __syncthreads();
    }

    int row = r0 + rr;
    float bias = fc_b[row];
    float v[4] = {acc0 + bias, acc1 + bias, acc2 + bias, acc3 + bias};
#pragma unroll
    for (int q = 0; q < 4; q++) {
        if (row < Hz) g_h0[(b0 + q) * Hz + row] = v[q];
        else          g_c[(b0 + q) * Hz + (row - Hz)] = v[q];
    }
}

// -------- input GEMM (fp32, exact): xW = emb[idx] @ W_ih^T + b_ih + b_hh --------
__global__ __launch_bounds__(256)
void sgemm_in_kernel(const float* __restrict__ emb, const float* __restrict__ Wih,
                     const float* __restrict__ bias, const float* __restrict__ bias2)
{
    __shared__ float As[8][128];
    __shared__ float Bs[8][128];

    const int N = 4 * Hz, K = Ez;
    int tid = threadIdx.x;
    int m0 = blockIdx.y * 128;
    int n0 = blockIdx.x * 128;

    int ldRow = tid >> 1;
    int ldK   = (tid & 1) * 4;

    const float* aBase = emb + (size_t)g_idx[m0 + ldRow] * K;
    const float* bBase = Wih + (size_t)(n0 + ldRow) * K;

    int ty = tid >> 4, tx = tid & 15;

    float acc[8][8];
#pragma unroll
    for (int i = 0; i < 8; i++)
#pragma unroll
        for (int j = 0; j < 8; j++) acc[i][j] = 0.f;

    for (int k0 = 0; k0 < K; k0 += 8) {
        float4 av = *(const float4*)(aBase + k0 + ldK);
        float4 bv = *(const float4*)(bBase + k0 + ldK);
        As[ldK + 0][ldRow] = av.x; As[ldK + 1][ldRow] = av.y;
        As[ldK + 2][ldRow] = av.z; As[ldK + 3][ldRow] = av.w;
        Bs[ldK + 0][ldRow] = bv.x; Bs[ldK + 1][ldRow] = bv.y;
        Bs[ldK + 2][ldRow] = bv.z; Bs[ldK + 3][ldRow] = bv.w;
        __syncthreads();
#pragma unroll
        for (int kk = 0; kk < 8; kk++) {
            float ar[8], br[8];
#pragma unroll
            for (int i = 0; i < 8; i++) ar[i] = As[kk][ty * 8 + i];
#pragma unroll
            for (int j = 0; j < 8; j++) br[j] = Bs[kk][tx * 8 + j];
#pragma unroll
            for (int i = 0; i < 8; i++)
#pragma unroll
                for (int j = 0; j < 8; j++) acc[i][j] += ar[i] * br[j];
        }
        __syncthreads();
    }

#pragma unroll
    for (int i = 0; i < 8; i++) {
        int m = m0 + ty * 8 + i;
        float* crow = g_xW + (size_t)m * N + n0 + tx * 8;
#pragma unroll
        for (int j = 0; j < 8; j++) {
            int n = n0 + tx * 8 + j;
            crow[j] = acc[i][j] + bias[n] + bias2[n];
        }
    }
}

// -------- stage 3: one LSTM step (fp32, float4-vectorized) --------
__global__ __launch_bounds__(256)
void lstm_step_kernel(const float* __restrict__ Whh, int t, int parity)
{
    __shared__ float4 ht4[32][32];   // h tile   [b][k4], 128 k per chunk
    __shared__ float4 wt4[32][33];   // Whh tile [gate-row][k4], stride 132 fl == 4 mod 32
    __shared__ float  gs[32][33];

    const float* h_in  = parity ? g_h1 : g_h0;
    float*       h_out = parity ? g_h0 : g_h1;

    int tid = threadIdx.x;
    int j0 = blockIdx.x * 8;
    int rr = tid & 31;
    int b0 = (tid >> 5) * 4;
    float acc0 = 0.f, acc1 = 0.f, acc2 = 0.f, acc3 = 0.f;

    for (int k0 = 0; k0 < Hz; k0 += 128) {
        for (int i = tid; i < 32 * 32; i += 256) {
            int b = i >> 5, k4 = i & 31;
            ht4[b][k4] = *(const float4*)(h_in + b * Hz + k0 + 4 * k4);
        }
        for (int i = tid; i < 32 * 32; i += 256) {
            int r = i >> 5, k4 = i & 31;
            int grow = (r >> 3) * Hz + j0 + (r & 7);
            wt4[r][k4] = *(const float4*)(Whh + (size_t)grow * Hz + k0 + 4 * k4);
        }
        __syncthreads();
#pragma unroll 8
        for (int k4 = 0; k4 < 32; k4++) {
            float4 w = wt4[rr][k4];
            float4 h0v = ht4[b0 + 0][k4], h1v = ht4[b0 + 1][k4];
            float4 h2v = ht4[b0 + 2][k4], h3v = ht4[b0 + 3][k4];
            acc0 += w.x * h0v.x + w.y * h0v.y + w.z * h0v.z + w.w * h0v.w;
            acc1 += w.x * h1v.x + w.y * h1v.y + w.z * h1v.z + w.w * h1v.w;
            acc2 += w.x * h2v.x + w.y * h2v.y + w.z * h2v.z + w.w * h2v.w;
            acc3 += w.x * h3v.x + w.y * h3v.y + w.z * h3v.z + w.w * h3v.w;
        }
        __syncthreads();
    }

    gs[b0 + 0][rr] = acc0;
    gs[b0 + 1][rr] = acc1;
    gs[b0 + 2][rr] = acc2;
    gs[b0 + 3][rr] = acc3;
    __syncthreads();

    int b = tid >> 3;
    int jj = tid & 7;
    size_t gbase = ((size_t)b * Tz + t) * (4 * Hz);
    float gi = gs[b][ 0 + jj] + g_xW[gbase + 0 * Hz + j0 + jj];
    float gf = gs[b][ 8 + jj] + g_xW[gbase + 1 * Hz + j0 + jj];
    float gg = gs[b][16 + jj] + g_xW[gbase + 2 * Hz + j0 + jj];
    float go = gs[b][24 + jj] + g_xW[gbase + 3 * Hz + j0 + jj];

    int hidx = b * Hz + j0 + jj;
    float cold = g_c[hidx];
    float cn = sigmoidf_(gf) * cold + sigmoidf_(gi) * tanhf(gg);
    float hn = sigmoidf_(go) * tanhf(cn);
    g_c[hidx] = cn;
    h_out[hidx] = hn;
    // store tf32-rounded copy for the tensor-core projection
    g_hs[((size_t)b * Tz + t) * Hz + j0 + jj] = round_tf32(hn);
}

// -------- stage 4: projection out = hs @ Wv^T + bv via TF32 mma.sync --------
// grid: x = M/128 = 32 (fast dim -> consecutive blocks reuse the same Wv tile),
//       y = N/128 = 125. Block tile 128x128, BK=16, double-buffered cp.async.
__global__ __launch_bounds__(256)
void proj_mma_kernel(const float* __restrict__ bv, float* __restrict__ out)
{
    __shared__ float As[2][128][20];   // [buf][m][k], pad 4 -> 16B-aligned rows, conflict-free
    __shared__ float Bs[2][128][20];   // [buf][n][k]

    const int N = Vz, K = Hz;
    int tid = threadIdx.x;
    int m0 = blockIdx.x * 128;
    int n0 = blockIdx.y * 128;

    int wid = tid >> 5, lane = tid & 31;
    int wm = (wid >> 2) * 64;          // warp m offset (0 or 64)
    int wn = (wid & 3) * 32;           // warp n offset (0,32,64,96)
    int gid = lane >> 2, tig = lane & 3;

    float acc[4][4][4];
#pragma unroll
    for (int i = 0; i < 4; i++)
#pragma unroll
        for (int j = 0; j < 4; j++)
#pragma unroll
            for (int q = 0; q < 4; q++) acc[i][j][q] = 0.f;

    int ldr = tid >> 2;                // 0..63  (x2 via +64)
    int ldc = (tid & 3) * 4;           // k-chunk within 16

    const int NT = K / 16;             // 64 k-tiles

    // prologue: load tile 0 into buf 0
    {
        const float* aS = g_hs + (size_t)(m0 + ldr) * K + ldc;
        const float* bS = g_Wv + (size_t)(n0 + ldr) * K + ldc;
        cpasync16(&As[0][ldr][ldc],      aS);
        cpasync16(&As[0][ldr + 64][ldc], aS + (size_t)64 * K);
        cpasync16(&Bs[0][ldr][ldc],      bS);
        cpasync16(&Bs[0][ldr + 64][ldc], bS + (size_t)64 * K);
        cpasync_commit();
    }

    for (int t = 0; t < NT; t++) {
        cpasync_wait0();
        __syncthreads();
        if (t + 1 < NT) {
            int nb = (t + 1) & 1;
            int k0 = (t + 1) * 16;
            const float* aS = g_hs + (size_t)(m0 + ldr) * K + k0 + ldc;
            const float* bS = g_Wv + (size_t)(n0 + ldr) * K + k0 + ldc;
            cpasync16(&As[nb][ldr][ldc],      aS);
            cpasync16(&As[nb][ldr + 64][ldc], aS + (size_t)64 * K);
            cpasync16(&Bs[nb][ldr][ldc],      bS);
            cpasync16(&Bs[nb][ldr + 64][ldc], bS + (size_t)64 * K);
            cpasync_commit();
        }
        int cb = t & 1;
#pragma unroll
        for (int ks = 0; ks < 2; ks++) {
            int kk = ks * 8;
            uint32_t a[4][4], b[4][2];
#pragma unroll
            for (int i = 0; i < 4; i++) {
                int r = wm + i * 16 + gid;
                a[i][0] = __float_as_uint(As[cb][r][kk + tig]);
                a[i][1] = __float_as_uint(As[cb][r + 8][kk + tig]);
                a[i][2] = __float_as_uint(As[cb][r][kk + tig + 4]);
                a[i][3] = __float_as_uint(As[cb][r + 8][kk + tig + 4]);
            }
#pragma unroll
            for (int j = 0; j < 4; j++) {
                int n = wn + j * 8 + gid;
                b[j][0] = __float_as_uint(Bs[cb][n][kk + tig]);
                b[j][1] = __float_as_uint(Bs[cb][n][kk + tig + 4]);
            }
#pragma unroll
            for (int i = 0; i < 4; i++)
#pragma unroll
                for (int j = 0; j < 4; j++)
                    mma_tf32(acc[i][j], a[i], b[j]);
        }
        __syncthreads();
    }

    // epilogue: add bias, write float2 pairs
#pragma unroll
    for (int j = 0; j < 4; j++) {
        int col = n0 + wn + j * 8 + tig * 2;
        float2 bvv = *(const float2*)(bv + col);
#pragma unroll
        for (int i = 0; i < 4; i++) {
            int r = m0 + wm + i * 16 + gid;
            float2 v0 = make_float2(acc[i][j][0] + bvv.x, acc[i][j][1] + bvv.y);
            float2 v1 = make_float2(acc[i][j][2] + bvv.x, acc[i][j][3] + bvv.y);
            *(float2*)(out + (size_t)r * N + col)       = v0;
            *(float2*)(out + (size_t)(r + 8) * N + col) = v1;
        }
    }
}

extern "C" void kernel_launch(void* const* d_in, const int* in_sizes, int n_in,
                              void* d_out, int out_size) {
    const float* features = (const float*)d_in[0];
    const int*   reports  = (const int*)d_in[1];
    const float* fc_W     = (const float*)d_in[2];
    const float* fc_b     = (const float*)d_in[3];
    const float* emb      = (const float*)d_in[4];
    const float* W_ih     = (const float*)d_in[5];
    const float* W_hh     = (const float*)d_in[6];
    const float* b_ih     = (const float*)d_in[7];
    const float* b_hh     = (const float*)d_in[8];
    const float* Wv       = (const float*)d_in[9];
    const float* bv       = (const float*)d_in[10];
    float* out = (float*)d_out;

    (void)in_sizes; (void)n_in; (void)out_size;

    pool_kernel<<<(Bz * Fz + 255) / 256, 256>>>(features);
    idx_kernel<<<(Bz * Tz + 255) / 256, 256>>>(reports);
    round_wv_kernel<<<(Vz * Hz + 255) / 256, 256>>>(Wv);

    init_kernel<<<64, 256>>>(fc_W, fc_b);

    {
        dim3 grid(4 * Hz / 128, Bz * Tz / 128);
        sgemm_in_kernel<<<grid, 256>>>(emb, W_ih, b_ih, b_hh);
    }

    for (int t = 0; t < Tz; t++) {
        lstm_step_kernel<<<Hz / 8, 256>>>(W_hh, t, t & 1);
    }

    {
        dim3 grid(Bz * Tz / 128, Vz / 128);
        proj_mma_kernel<<<grid, 256>>>(bv, out);
    }
}

// round 5
// speedup vs baseline: 2.3687x; 1.2706x over previous
#include <cuda_runtime.h>
#include <math.h>
#include <stdint.h>

#define Bz 32
#define Tz 128
#define Vz 16000
#define Ez 512
#define Hz 1024
#define Fz 2048
#define NBLK 128                      // persistent LSTM blocks (<=148 SMs, all resident)

// -------- scratch (static device globals; no runtime allocation) --------
__device__ float g_pooled[Bz * Fz];
__device__ float g_h0[Bz * Hz];
__device__ float g_h1[Bz * Hz];
__device__ float g_c[Bz * Hz];
__device__ float g_xW[Bz * Tz * 4 * Hz];   // 64 MB input-gate preactivations
__device__ float g_hs[Bz * Tz * Hz];       // 16 MB hidden states (tf32-rounded)
__device__ float g_Wv[Vz * Hz];            // Wv tf32-rounded
__device__ float g_embt[Vz * Ez];          // emb tf32-rounded
__device__ float g_Wih[4 * Hz * Ez];       // W_ih tf32-rounded
__device__ float g_bihh[4 * Hz];           // b_ih + b_hh
__device__ int   g_idx[Bz * Tz];
__device__ unsigned g_bar;

__device__ __forceinline__ float sigmoidf_(float x) {
    return 1.0f / (1.0f + expf(-x));
}
__device__ __forceinline__ float round_tf32(float x) {
    uint32_t u;
    asm("cvt.rna.tf32.f32 %0, %1;" : "=r"(u) : "f"(x));
    return __uint_as_float(u);
}
__device__ __forceinline__ void cpasync16(void* dst, const void* src) {
    uint32_t d = (uint32_t)__cvta_generic_to_shared(dst);
    asm volatile("cp.async.cg.shared.global [%0], [%1], 16;" :: "r"(d), "l"(src));
}
__device__ __forceinline__ void cpasync_commit() { asm volatile("cp.async.commit_group;"); }
__device__ __forceinline__ void cpasync_wait0()  { asm volatile("cp.async.wait_group 0;"); }

__device__ __forceinline__ void mma_tf32(float* c, const uint32_t* a, const uint32_t* b) {
    asm volatile(
        "mma.sync.aligned.m16n8k8.row.col.f32.tf32.tf32.f32 "
        "{%0,%1,%2,%3}, {%4,%5,%6,%7}, {%8,%9}, {%0,%1,%2,%3};"
        : "+f"(c[0]), "+f"(c[1]), "+f"(c[2]), "+f"(c[3])
        : "r"(a[0]), "r"(a[1]), "r"(a[2]), "r"(a[3]), "r"(b[0]), "r"(b[1]));
}

// ==================== small prep kernels ====================
__global__ void reset_bar_kernel() { g_bar = 0u; }

__global__ void pool_kernel(const float* __restrict__ features) {
    int n = blockIdx.x * blockDim.x + threadIdx.x;
    if (n >= Bz * Fz) return;
    const float* p = features + (size_t)n * 49;
    float s = 0.f;
#pragma unroll
    for (int i = 0; i < 49; i++) s += p[i];
    g_pooled[n] = s * (1.0f / 49.0f);
}

__global__ void idx_kernel(const int* __restrict__ reports) {
    int n = blockIdx.x * blockDim.x + threadIdx.x;
    if (n >= Bz * Tz) return;
    int t = n & (Tz - 1);
    g_idx[n] = (t == 0) ? 1 : reports[n - 1];        // START_IDX = 1
}

// mode 0 -> g_Wv, 1 -> g_embt, 2 -> g_Wih
__global__ void round_kernel(const float* __restrict__ src, int n, int mode) {
    int i = blockIdx.x * blockDim.x + threadIdx.x;
    if (i >= n) return;
    float* dst = (mode == 0) ? g_Wv : (mode == 1) ? g_embt : g_Wih;
    dst[i] = round_tf32(src[i]);
}

__global__ void bias_kernel(const float* __restrict__ b_ih, const float* __restrict__ b_hh) {
    int i = blockIdx.x * blockDim.x + threadIdx.x;
    if (i < 4 * Hz) g_bihh[i] = b_ih[i] + b_hh[i];
}

// ==================== init: h0,c0 = pooled @ fc_W^T + fc_b ====================
__global__ __launch_bounds__(256)
void init_kernel(const float* __restrict__ fc_W, const float* __restrict__ fc_b) {
    __shared__ float4 sp4[32][32];
    __shared__ float4 wt4[16][33];

    int tid = threadIdx.x;
    int r0 = blockIdx.x * 16;
    int rr = tid & 15;
    int b0 = (tid >> 4) * 2;
    float acc0 = 0.f, acc1 = 0.f;

    for (int k0 = 0; k0 < Fz; k0 += 128) {
        for (int i = tid; i < 32 * 32; i += 256) {
            int b = i >> 5, k4 = i & 31;
            sp4[b][k4] = *(const float4*)(g_pooled + b * Fz + k0 + 4 * k4);
        }
        for (int i = tid; i < 16 * 32; i += 256) {
            int r = i >> 5, k4 = i & 31;
            wt4[r][k4] = *(const float4*)(fc_W + (size_t)(r0 + r) * Fz + k0 + 4 * k4);
        }
        __syncthreads();
#pragma unroll 8
        for (int k4 = 0; k4 < 32; k4++) {
            float4 w = wt4[rr][k4];
            float4 p0 = sp4[b0][k4], p1 = sp4[b0 + 1][k4];
            acc0 += w.x * p0.x + w.y * p0.y + w.z * p0.z + w.w * p0.w;
            acc1 += w.x * p1.x + w.y * p1.y + w.z * p1.z + w.w * p1.w;
        }
        __syncthreads();
    }

    int row = r0 + rr;
    float bias = fc_b[row];
    if (row < Hz) {
        g_h0[b0 * Hz + row] = acc0 + bias;
        g_h0[(b0 + 1) * Hz + row] = acc1 + bias;
    } else {
        g_c[b0 * Hz + (row - Hz)] = acc0 + bias;
        g_c[(b0 + 1) * Hz + (row - Hz)] = acc1 + bias;
    }
}

// ==================== generic TF32 tensor-core GEMM ====================
// MODE 0: g_xW = g_embt[g_idx rows] @ g_Wih^T + g_bihh   (M=4096, N=4096, K=512)
// MODE 1: out  = g_hs @ g_Wv^T + bias                    (M=4096, N=16000, K=1024)
template<int MODE>
__global__ __launch_bounds__(256)
void gemm_tf32_kernel(const float* __restrict__ bias, float* __restrict__ outp)
{
    __shared__ float As[2][128][20];
    __shared__ float Bs[2][128][20];

    constexpr int K = (MODE == 0) ? Ez : Hz;
    constexpr int N = (MODE == 0) ? 4 * Hz : Vz;
    const float* A  = (MODE == 0) ? g_embt : g_hs;
    const float* Bw = (MODE == 0) ? g_Wih : g_Wv;
    float* C        = (MODE == 0) ? g_xW : outp;
    const float* bias_p = (MODE == 0) ? g_bihh : bias;   // <-- R4 fix (was nullptr deref)

    int tid = threadIdx.x;
    int m0 = blockIdx.x * 128;
    int n0 = blockIdx.y * 128;

    int wid = tid >> 5, lane = tid & 31;
    int wm = (wid >> 2) * 64;
    int wn = (wid & 3) * 32;
    int gid = lane >> 2, tig = lane & 3;

    float acc[4][4][4];
#pragma unroll
    for (int i = 0; i < 4; i++)
#pragma unroll
        for (int j = 0; j < 4; j++)
#pragma unroll
            for (int q = 0; q < 4; q++) acc[i][j][q] = 0.f;

    int ldr = tid >> 2;
    int ldc = (tid & 3) * 4;

    const float* aRow0;
    const float* aRow1;
    if (MODE == 0) {
        aRow0 = A + (size_t)g_idx[m0 + ldr] * K;
        aRow1 = A + (size_t)g_idx[m0 + ldr + 64] * K;
    } else {
        aRow0 = A + (size_t)(m0 + ldr) * K;
        aRow1 = aRow0 + (size_t)64 * K;
    }
    const float* bRow0 = Bw + (size_t)(n0 + ldr) * K;
    const float* bRow1 = bRow0 + (size_t)64 * K;

    const int NT = K / 16;

    cpasync16(&As[0][ldr][ldc],      aRow0 + ldc);
    cpasync16(&As[0][ldr + 64][ldc], aRow1 + ldc);
    cpasync16(&Bs[0][ldr][ldc],      bRow0 + ldc);
    cpasync16(&Bs[0][ldr + 64][ldc], bRow1 + ldc);
    cpasync_commit();

    for (int t = 0; t < NT; t++) {
        cpasync_wait0();
        __syncthreads();
        if (t + 1 < NT) {
            int nb = (t + 1) & 1;
            int k0 = (t + 1) * 16 + ldc;
            cpasync16(&As[nb][ldr][ldc],      aRow0 + k0);
            cpasync16(&As[nb][ldr + 64][ldc], aRow1 + k0);
            cpasync16(&Bs[nb][ldr][ldc],      bRow0 + k0);
            cpasync16(&Bs[nb][ldr + 64][ldc], bRow1 + k0);
            cpasync_commit();
        }
        int cb = t & 1;
#pragma unroll
        for (int ks = 0; ks < 2; ks++) {
            int kk = ks * 8;
            uint32_t a[4][4], b[4][2];
#pragma unroll
            for (int i = 0; i < 4; i++) {
                int r = wm + i * 16 + gid;
                a[i][0] = __float_as_uint(As[cb][r][kk + tig]);
                a[i][1] = __float_as_uint(As[cb][r + 8][kk + tig]);
                a[i][2] = __float_as_uint(As[cb][r][kk + tig + 4]);
                a[i][3] = __float_as_uint(As[cb][r + 8][kk + tig + 4]);
            }
#pragma unroll
            for (int j = 0; j < 4; j++) {
                int n = wn + j * 8 + gid;
                b[j][0] = __float_as_uint(Bs[cb][n][kk + tig]);
                b[j][1] = __float_as_uint(Bs[cb][n][kk + tig + 4]);
            }
#pragma unroll
            for (int i = 0; i < 4; i++)
#pragma unroll
                for (int j = 0; j < 4; j++)
                    mma_tf32(acc[i][j], a[i], b[j]);
        }
        __syncthreads();
    }

#pragma unroll
    for (int j = 0; j < 4; j++) {
        int col = n0 + wn + j * 8 + tig * 2;
        float2 bvv = *(const float2*)(bias_p + col);
#pragma unroll
        for (int i = 0; i < 4; i++) {
            int r = m0 + wm + i * 16 + gid;
            float2 v0 = make_float2(acc[i][j][0] + bvv.x, acc[i][j][1] + bvv.y);
            float2 v1 = make_float2(acc[i][j][2] + bvv.x, acc[i][j][3] + bvv.y);
            *(float2*)(C + (size_t)r * N + col)       = v0;
            *(float2*)(C + (size_t)(r + 8) * N + col) = v1;
        }
    }
}

// ==================== persistent LSTM: all 128 steps, one kernel ====================
// 128 blocks x 256 thr. Block bx owns h columns [bx*8, bx*8+8), all gates, all batches.
// W_hh slice (32 rows x 1024) cached in smem once; c kept in registers.
// Grid barrier between steps (all blocks resident: 1 block/SM by smem).
#define WSTRIDE 1028                                  // 1024 + 4 -> conflict-free LDS.128
#define SMEM_LSTM (size_t)((32 * WSTRIDE + 4096 + 32 * 33) * 4)

__global__ __launch_bounds__(256)
void lstm_persistent(const float* __restrict__ Whh)
{
    extern __shared__ float sm[];
    float* wt  = sm;                                  // [32][WSTRIDE]
    float* hpf = sm + 32 * WSTRIDE;                   // packed h pairs: [128 k][16 pair] f32x2
    unsigned long long* hp = (unsigned long long*)hpf;
    float* gs  = hpf + 4096;                          // [32][33]

    int tid = threadIdx.x;
    int j0 = blockIdx.x * 8;
    int rr = tid & 31;                 // gate-row within block (gate=rr>>3, jj=rr&7)
    int p0 = (tid >> 5) * 2;           // batch-pair base -> batches 2*p0 .. 2*p0+3
    int bb = tid >> 3;                 // gate-update batch
    int jj = tid & 7;

    // cache W_hh slice (rows q*Hz + j0 + jj for q in 0..3)
    for (int i = tid; i < 32 * 256; i += 256) {
        int r = i >> 8, k4 = i & 255;
        int grow = (r >> 3) * Hz + j0 + (r & 7);
        *(float4*)(wt + r * WSTRIDE + 4 * k4) =
            *(const float4*)(Whh + (size_t)grow * Hz + 4 * k4);
    }
    float c_reg = g_c[bb * Hz + j0 + jj];
    __syncthreads();

    for (int t = 0; t < Tz; t++) {
        const float* h_in  = (t & 1) ? g_h1 : g_h0;
        float*       h_out = (t & 1) ? g_h0 : g_h1;

        // prefetch this thread's xW preactivations (consumed after the K loop)
        size_t gbase = ((size_t)bb * Tz + t) * (4 * Hz);
        float xi = __ldcs(&g_xW[gbase + 0 * Hz + j0 + jj]);
        float xf = __ldcs(&g_xW[gbase + 1 * Hz + j0 + jj]);
        float xg = __ldcs(&g_xW[gbase + 2 * Hz + j0 + jj]);
        float xo = __ldcs(&g_xW[gbase + 3 * Hz + j0 + jj]);

        unsigned long long acc01 = 0ull, acc23 = 0ull;   // {0.f,0.f}

        for (int k0 = 0; k0 < Hz; k0 += 128) {
            __syncthreads();
            // stage h chunk, transposed into batch-pair layout
#pragma unroll
            for (int it = 0; it < 4; it++) {
                int idx = tid + it * 256;
                int b = idx & 31, k4 = idx >> 5;
                float4 v = __ldcg((const float4*)(h_in + b * Hz + k0 + 4 * k4));
                int pr = (b >> 1), lsb = (b & 1);
                hpf[((k4 * 4 + 0) * 16 + pr) * 2 + lsb] = v.x;
                hpf[((k4 * 4 + 1) * 16 + pr) * 2 + lsb] = v.y;
                hpf[((k4 * 4 + 2) * 16 + pr) * 2 + lsb] = v.z;
                hpf[((k4 * 4 + 3) * 16 + pr) * 2 + lsb] = v.w;
            }
            __syncthreads();

            const float* wrow = wt + rr * WSTRIDE + k0;
#pragma unroll 8
            for (int k4 = 0; k4 < 32; k4++) {
                float4 w = *(const float4*)(wrow + 4 * k4);
#pragma unroll
                for (int kk = 0; kk < 4; kk++) {
                    float wk = (kk == 0) ? w.x : (kk == 1) ? w.y : (kk == 2) ? w.z : w.w;
                    unsigned long long w2;
                    asm("mov.b64 %0, {%1, %1};" : "=l"(w2) : "f"(wk));
                    ulonglong2 hv = *(const ulonglong2*)(hp + (k4 * 4 + kk) * 16 + p0);
                    asm("fma.rn.f32x2 %0, %1, %2, %0;" : "+l"(acc01) : "l"(w2), "l"(hv.x));
                    asm("fma.rn.f32x2 %0, %1, %2, %0;" : "+l"(acc23) : "l"(w2), "l"(hv.y));
                }
            }
        }

        float a0, a1, a2, a3;
        asm("mov.b64 {%0, %1}, %2;" : "=f"(a0), "=f"(a1) : "l"(acc01));
        asm("mov.b64 {%0, %1}, %2;" : "=f"(a2), "=f"(a3) : "l"(acc23));
        __syncthreads();
        gs[(2 * p0 + 0) * 33 + rr] = a0;
        gs[(2 * p0 + 1) * 33 + rr] = a1;
        gs[(2 * p0 + 2) * 33 + rr] = a2;
        gs[(2 * p0 + 3) * 33 + rr] = a3;
        __syncthreads();

        float gi = gs[bb * 33 +  0 + jj] + xi;
        float gf = gs[bb * 33 +  8 + jj] + xf;
        float gg = gs[bb * 33 + 16 + jj] + xg;
        float go = gs[bb * 33 + 24 + jj] + xo;

        float cn = sigmoidf_(gf) * c_reg + sigmoidf_(gi) * tanhf(gg);
        float hn = sigmoidf_(go) * tanhf(cn);
        c_reg = cn;
        __stcg(h_out + bb * Hz + j0 + jj, hn);
        g_hs[((size_t)bb * Tz + t) * Hz + j0 + jj] = round_tf32(hn);

        // grid barrier
        __threadfence();
        __syncthreads();
        if (tid == 0) {
            unsigned target = (unsigned)(t + 1) * (unsigned)gridDim.x;
            atomicAdd(&g_bar, 1u);
            while (*(volatile unsigned*)&g_bar < target) __nanosleep(64);
        }
        __syncthreads();
    }
}

// ==================== launcher ====================
extern "C" void kernel_launch(void* const* d_in, const int* in_sizes, int n_in,
                              void* d_out, int out_size) {
    const float* features = (const float*)d_in[0];
    const int*   reports  = (const int*)d_in[1];
    const float* fc_W     = (const float*)d_in[2];
    const float* fc_b     = (const float*)d_in[3];
    const float* emb      = (const float*)d_in[4];
    const float* W_ih     = (const float*)d_in[5];
    const float* W_hh     = (const float*)d_in[6];
    const float* b_ih     = (const float*)d_in[7];
    const float* b_hh     = (const float*)d_in[8];
    const float* Wv       = (const float*)d_in[9];
    const float* bv       = (const float*)d_in[10];
    float* out = (float*)d_out;

    (void)in_sizes; (void)n_in; (void)out_size;

    cudaFuncSetAttribute(lstm_persistent,
                         cudaFuncAttributeMaxDynamicSharedMemorySize, (int)SMEM_LSTM);

    reset_bar_kernel<<<1, 1>>>();
    pool_kernel<<<(Bz * Fz + 255) / 256, 256>>>(features);
    idx_kernel<<<(Bz * Tz + 255) / 256, 256>>>(reports);
    round_kernel<<<(Vz * Hz + 255) / 256, 256>>>(Wv, Vz * Hz, 0);
    round_kernel<<<(Vz * Ez + 255) / 256, 256>>>(emb, Vz * Ez, 1);
    round_kernel<<<(4 * Hz * Ez + 255) / 256, 256>>>(W_ih, 4 * Hz * Ez, 2);
    bias_kernel<<<(4 * Hz + 255) / 256, 256>>>(b_ih, b_hh);

    init_kernel<<<128, 256>>>(fc_W, fc_b);

    // input GEMM: xW = emb[idx] @ W_ih^T + (b_ih + b_hh)
    gemm_tf32_kernel<0><<<dim3(Bz * Tz / 128, 4 * Hz / 128), 256>>>(nullptr, nullptr);

    // persistent LSTM over all 128 timesteps
    lstm_persistent<<<NBLK, 256, SMEM_LSTM>>>(W_hh);

    // projection: out = hs @ Wv^T + bv
    gemm_tf32_kernel<1><<<dim3(Bz * Tz / 128, Vz / 128), 256>>>(bv, out);
}

// round 6
// speedup vs baseline: 3.1490x; 1.3294x over previous
#include <cuda_runtime.h>
#include <math.h>
#include <stdint.h>

#define Bz 32
#define Tz 128
#define Vz 16000
#define Ez 512
#define Hz 1024
#define Fz 2048
#define NBLK 128

// -------- scratch (static device globals; no runtime allocation) --------
__device__ float g_pooled[Bz * Fz];
__device__ float g_h0[Bz * Hz];
__device__ float g_h1[Bz * Hz];
__device__ float g_c[Bz * Hz];
__device__ float g_xW[Bz * Tz * 4 * Hz];   // 64 MB input-gate preactivations
__device__ float g_hs[Bz * Tz * Hz];       // hidden states (tf32-rounded)
__device__ float g_Wv[Vz * Hz];            // Wv tf32-rounded
__device__ float g_embt[Vz * Ez];          // emb tf32-rounded
__device__ float g_Wih[4 * Hz * Ez];       // W_ih tf32-rounded
__device__ float g_bihh[4 * Hz];           // b_ih + b_hh
__device__ int   g_idx[Bz * Tz];
__device__ int   g_flags[NBLK];            // grid-barrier flags (one per block)

__device__ __forceinline__ float sigmoidf_(float x) {
    return 1.0f / (1.0f + expf(-x));
}
__device__ __forceinline__ float round_tf32(float x) {
    uint32_t u;
    asm("cvt.rna.tf32.f32 %0, %1;" : "=r"(u) : "f"(x));
    return __uint_as_float(u);
}
__device__ __forceinline__ void cpasync16(void* dst, const void* src) {
    uint32_t d = (uint32_t)__cvta_generic_to_shared(dst);
    asm volatile("cp.async.cg.shared.global [%0], [%1], 16;" :: "r"(d), "l"(src));
}
__device__ __forceinline__ void cpasync_commit() { asm volatile("cp.async.commit_group;"); }
__device__ __forceinline__ void cpasync_wait0()  { asm volatile("cp.async.wait_group 0;"); }

__device__ __forceinline__ void mma_tf32(float* c, const uint32_t* a, const uint32_t* b) {
    asm volatile(
        "mma.sync.aligned.m16n8k8.row.col.f32.tf32.tf32.f32 "
        "{%0,%1,%2,%3}, {%4,%5,%6,%7}, {%8,%9}, {%0,%1,%2,%3};"
        : "+f"(c[0]), "+f"(c[1]), "+f"(c[2]), "+f"(c[3])
        : "r"(a[0]), "r"(a[1]), "r"(a[2]), "r"(a[3]), "r"(b[0]), "r"(b[1]));
}
__device__ __forceinline__ void ffma2(unsigned long long& acc,
                                      unsigned long long a, unsigned long long b) {
    asm("fma.rn.f32x2 %0, %1, %2, %0;" : "+l"(acc) : "l"(a), "l"(b));
}

// ==================== launch 0: fused small prep ====================
__global__ void prep_kernel(const float* __restrict__ features,
                            const int* __restrict__ reports,
                            const float* __restrict__ b_ih,
                            const float* __restrict__ b_hh) {
    int n = blockIdx.x * blockDim.x + threadIdx.x;   // 65536 threads
    if (n < Bz * Fz) {
        const float* p = features + (size_t)n * 49;
        float s = 0.f;
#pragma unroll
        for (int i = 0; i < 49; i++) s += p[i];
        g_pooled[n] = s * (1.0f / 49.0f);
    }
    if (n < Bz * Tz) {
        int t = n & (Tz - 1);
        g_idx[n] = (t == 0) ? 1 : reports[n - 1];    // START_IDX = 1
    }
    if (n < 4 * Hz) g_bihh[n] = b_ih[n] + b_hh[n];
    if (n < NBLK) g_flags[n] = 0;
}

// ==================== launch 1: fused tf32 rounding ====================
__global__ void round_all_kernel(const float* __restrict__ Wv,
                                 const float* __restrict__ emb,
                                 const float* __restrict__ Wih) {
    int i = blockIdx.x * blockDim.x + threadIdx.x;
    if (i < Vz * Hz) { g_Wv[i] = round_tf32(Wv[i]); return; }
    i -= Vz * Hz;
    if (i < Vz * Ez) { g_embt[i] = round_tf32(emb[i]); return; }
    i -= Vz * Ez;
    if (i < 4 * Hz * Ez) g_Wih[i] = round_tf32(Wih[i]);
}

// ==================== launch 2: init h0,c0 = pooled @ fc_W^T + fc_b ====================
__global__ __launch_bounds__(256)
void init_kernel(const float* __restrict__ fc_W, const float* __restrict__ fc_b) {
    __shared__ float4 sp4[32][32];
    __shared__ float4 wt4[16][33];

    int tid = threadIdx.x;
    int r0 = blockIdx.x * 16;
    int rr = tid & 15;
    int b0 = (tid >> 4) * 2;
    float acc0 = 0.f, acc1 = 0.f;

    for (int k0 = 0; k0 < Fz; k0 += 128) {
        for (int i = tid; i < 32 * 32; i += 256) {
            int b = i >> 5, k4 = i & 31;
            sp4[b][k4] = *(const float4*)(g_pooled + b * Fz + k0 + 4 * k4);
        }
        for (int i = tid; i < 16 * 32; i += 256) {
            int r = i >> 5, k4 = i & 31;
            wt4[r][k4] = *(const float4*)(fc_W + (size_t)(r0 + r) * Fz + k0 + 4 * k4);
        }
        __syncthreads();
#pragma unroll 8
        for (int k4 = 0; k4 < 32; k4++) {
            float4 w = wt4[rr][k4];
            float4 p0 = sp4[b0][k4], p1 = sp4[b0 + 1][k4];
            acc0 += w.x * p0.x + w.y * p0.y + w.z * p0.z + w.w * p0.w;
            acc1 += w.x * p1.x + w.y * p1.y + w.z * p1.z + w.w * p1.w;
        }
        __syncthreads();
    }

    int row = r0 + rr;
    float bias = fc_b[row];
    if (row < Hz) {
        g_h0[b0 * Hz + row] = acc0 + bias;
        g_h0[(b0 + 1) * Hz + row] = acc1 + bias;
    } else {
        g_c[b0 * Hz + (row - Hz)] = acc0 + bias;
        g_c[(b0 + 1) * Hz + (row - Hz)] = acc1 + bias;
    }
}

// ==================== TF32 tensor-core GEMM (launches 3 and 5) ====================
// MODE 0: g_xW = g_embt[g_idx rows] @ g_Wih^T + g_bihh   (M=4096, N=4096, K=512)
// MODE 1: out  = g_hs @ g_Wv^T + bias                    (M=4096, N=16000, K=1024)
// Rows strided 24 floats (16 data + 8 pad) -> conflict-free LDS.64 frag loads.
// k-slot remap: lane tig uses physical k {2tig, 2tig+1} (consistent across A & B).
#define GROW 24
#define GEMM_SMEM (size_t)(4 * 128 * GROW * sizeof(float))   // 2 arrays x 2 bufs

template<int MODE>
__global__ __launch_bounds__(256)
void gemm_tf32_kernel(const float* __restrict__ bias, float* __restrict__ outp)
{
    extern __shared__ float psm[];
    float* Asm = psm;                       // [2][128*GROW]
    float* Bsm = psm + 2 * 128 * GROW;      // [2][128*GROW]

    constexpr int K = (MODE == 0) ? Ez : Hz;
    constexpr int N = (MODE == 0) ? 4 * Hz : Vz;
    const float* A  = (MODE == 0) ? g_embt : g_hs;
    const float* Bw = (MODE == 0) ? g_Wih : g_Wv;
    float* C        = (MODE == 0) ? g_xW : outp;
    const float* bias_p = (MODE == 0) ? g_bihh : bias;

    int tid = threadIdx.x;
    int m0 = blockIdx.x * 128;
    int n0 = blockIdx.y * 128;

    int wid = tid >> 5, lane = tid & 31;
    int wm = (wid >> 2) * 64;
    int wn = (wid & 3) * 32;
    int gid = lane >> 2, tig = lane & 3;

    float acc[4][4][4];
#pragma unroll
    for (int i = 0; i < 4; i++)
#pragma unroll
        for (int j = 0; j < 4; j++)
#pragma unroll
            for (int q = 0; q < 4; q++) acc[i][j][q] = 0.f;

    int ldr = tid >> 2;
    int ldc = (tid & 3) * 4;

    const float* aRow0;
    const float* aRow1;
    if (MODE == 0) {
        aRow0 = A + (size_t)g_idx[m0 + ldr] * K;
        aRow1 = A + (size_t)g_idx[m0 + ldr + 64] * K;
    } else {
        aRow0 = A + (size_t)(m0 + ldr) * K;
        aRow1 = aRow0 + (size_t)64 * K;
    }
    const float* bRow0 = Bw + (size_t)(n0 + ldr) * K;
    const float* bRow1 = bRow0 + (size_t)64 * K;

    const int NT = K / 16;

    cpasync16(&Asm[ldr * GROW + ldc],        aRow0 + ldc);
    cpasync16(&Asm[(ldr + 64) * GROW + ldc], aRow1 + ldc);
    cpasync16(&Bsm[ldr * GROW + ldc],        bRow0 + ldc);
    cpasync16(&Bsm[(ldr + 64) * GROW + ldc], bRow1 + ldc);
    cpasync_commit();

    for (int t = 0; t < NT; t++) {
        cpasync_wait0();
        __syncthreads();
        if (t + 1 < NT) {
            int nb = ((t + 1) & 1) * 128 * GROW;
            int k0 = (t + 1) * 16 + ldc;
            cpasync16(&Asm[nb + ldr * GROW + ldc],        aRow0 + k0);
            cpasync16(&Asm[nb + (ldr + 64) * GROW + ldc], aRow1 + k0);
            cpasync16(&Bsm[nb + ldr * GROW + ldc],        bRow0 + k0);
            cpasync16(&Bsm[nb + (ldr + 64) * GROW + ldc], bRow1 + k0);
            cpasync_commit();
        }
        int cb = (t & 1) * 128 * GROW;
#pragma unroll
        for (int ks = 0; ks < 2; ks++) {
            int kk = ks * 8 + 2 * tig;
            uint32_t a[4][4], b[4][2];
#pragma unroll
            for (int i = 0; i < 4; i++) {
                int r = wm + i * 16 + gid;
                float2 av0 = *(const float2*)(&Asm[cb + r * GROW + kk]);
                float2 av1 = *(const float2*)(&Asm[cb + (r + 8) * GROW + kk]);
                a[i][0] = __float_as_uint(av0.x);
                a[i][1] = __float_as_uint(av1.x);
                a[i][2] = __float_as_uint(av0.y);
                a[i][3] = __float_as_uint(av1.y);
            }
#pragma unroll
            for (int j = 0; j < 4; j++) {
                int n = wn + j * 8 + gid;
                float2 bv2 = *(const float2*)(&Bsm[cb + n * GROW + kk]);
                b[j][0] = __float_as_uint(bv2.x);
                b[j][1] = __float_as_uint(bv2.y);
            }
#pragma unroll
            for (int i = 0; i < 4; i++)
#pragma unroll
                for (int j = 0; j < 4; j++)
                    mma_tf32(acc[i][j], a[i], b[j]);
        }
        __syncthreads();
    }

#pragma unroll
    for (int j = 0; j < 4; j++) {
        int col = n0 + wn + j * 8 + tig * 2;
        float2 bvv = *(const float2*)(bias_p + col);
#pragma unroll
        for (int i = 0; i < 4; i++) {
            int r = m0 + wm + i * 16 + gid;
            float2 v0 = make_float2(acc[i][j][0] + bvv.x, acc[i][j][1] + bvv.y);
            float2 v1 = make_float2(acc[i][j][2] + bvv.x, acc[i][j][3] + bvv.y);
            *(float2*)(C + (size_t)r * N + col)       = v0;
            *(float2*)(C + (size_t)(r + 8) * N + col) = v1;
        }
    }
}

// ==================== launch 4: persistent LSTM, all 128 steps ====================
// 128 blocks x 256 thr, 1 block/SM (smem-forced). Block bx owns h cols [bx*8, bx*8+8).
// Warp w <-> batches 4w..4w+3 (h loads are warp-broadcast). Lane <-> gate-row.
// f32x2 pairs over (k even, k odd): w pairs straight from wt, h pairs from natural layout.
#define WSTRIDE 1028                       // 1024+4 floats -> conflict-free LDS.128 rows
#define HSTRIDE 264                        // 256+8
#define CHUNK 256
#define SMEM_LSTM (size_t)((32 * WSTRIDE + 2 * 32 * HSTRIDE + 32 * 33) * sizeof(float))

__global__ __launch_bounds__(256)
void lstm_persistent(const float* __restrict__ Whh)
{
    extern __shared__ float sm[];
    float* wt  = sm;                               // [32][WSTRIDE]
    float* hsm = sm + 32 * WSTRIDE;                // [2][32][HSTRIDE]
    float* gs  = hsm + 2 * 32 * HSTRIDE;           // [32][33]

    int tid = threadIdx.x;
    int bx = blockIdx.x;
    int j0 = bx * 8;
    int rr = tid & 31;                 // gate-row within block
    int wg = tid >> 5;                 // warp -> batches 4wg..4wg+3
    int bb = tid >> 3;                 // elementwise batch
    int jj = tid & 7;                  // elementwise column

    // cache W_hh slice once: row r holds gate (r>>3), col j0+(r&7)
    for (int i = tid; i < 32 * 256; i += 256) {
        int r = i >> 8, k4 = i & 255;
        int grow = (r >> 3) * Hz + j0 + (r & 7);
        *(float4*)(wt + r * WSTRIDE + 4 * k4) =
            *(const float4*)(Whh + (size_t)grow * Hz + 4 * k4);
    }
    float c_reg = g_c[bb * Hz + j0 + jj];
    __syncthreads();

    for (int t = 0; t < Tz; t++) {
        const float* h_in  = (t & 1) ? g_h1 : g_h0;
        float*       h_out = (t & 1) ? g_h0 : g_h1;

        // prefetch xW preactivations
        size_t gbase = ((size_t)bb * Tz + t) * (4 * Hz);
        float xi = __ldcs(&g_xW[gbase + 0 * Hz + j0 + jj]);
        float xf = __ldcs(&g_xW[gbase + 1 * Hz + j0 + jj]);
        float xg = __ldcs(&g_xW[gbase + 2 * Hz + j0 + jj]);
        float xo = __ldcs(&g_xW[gbase + 3 * Hz + j0 + jj]);

        unsigned long long acc[4] = {0ull, 0ull, 0ull, 0ull};

        // stage chunk 0 into buf 0 (cp.async reads at L2 -> coherent with stcg)
#pragma unroll
        for (int it = 0; it < 8; it++) {
            int idx = tid + it * 256;
            int b = idx >> 6, k4 = idx & 63;
            cpasync16(hsm + b * HSTRIDE + 4 * k4, h_in + b * Hz + 4 * k4);
        }
        cpasync_commit();

        for (int c = 0; c < Hz / CHUNK; c++) {
            cpasync_wait0();
            __syncthreads();
            if (c + 1 < Hz / CHUNK) {
                float* hb = hsm + ((c + 1) & 1) * 32 * HSTRIDE;
                const float* hg = h_in + (c + 1) * CHUNK;
#pragma unroll
                for (int it = 0; it < 8; it++) {
                    int idx = tid + it * 256;
                    int b = idx >> 6, k4 = idx & 63;
                    cpasync16(hb + b * HSTRIDE + 4 * k4, hg + b * Hz + 4 * k4);
                }
                cpasync_commit();
            }
            const float* wrow = wt + rr * WSTRIDE + c * CHUNK;
            const float* hb = hsm + (c & 1) * 32 * HSTRIDE;
            const float* h0r = hb + (4 * wg + 0) * HSTRIDE;
            const float* h1r = hb + (4 * wg + 1) * HSTRIDE;
            const float* h2r = hb + (4 * wg + 2) * HSTRIDE;
            const float* h3r = hb + (4 * wg + 3) * HSTRIDE;
#pragma unroll 8
            for (int k4 = 0; k4 < CHUNK / 4; k4++) {
                ulonglong2 wv = *(const ulonglong2*)(wrow + 4 * k4);
                ulonglong2 h0v = *(const ulonglong2*)(h0r + 4 * k4);
                ulonglong2 h1v = *(const ulonglong2*)(h1r + 4 * k4);
                ulonglong2 h2v = *(const ulonglong2*)(h2r + 4 * k4);
                ulonglong2 h3v = *(const ulonglong2*)(h3r + 4 * k4);
                ffma2(acc[0], wv.x, h0v.x); ffma2(acc[0], wv.y, h0v.y);
                ffma2(acc[1], wv.x, h1v.x); ffma2(acc[1], wv.y, h1v.y);
                ffma2(acc[2], wv.x, h2v.x); ffma2(acc[2], wv.y, h2v.y);
                ffma2(acc[3], wv.x, h3v.x); ffma2(acc[3], wv.y, h3v.y);
            }
        }

        __syncthreads();
#pragma unroll
        for (int q = 0; q < 4; q++) {
            float lo, hi;
            asm("mov.b64 {%0, %1}, %2;" : "=f"(lo), "=f"(hi) : "l"(acc[q]));
            gs[(4 * wg + q) * 33 + rr] = lo + hi;
        }
        __syncthreads();

        float gi = gs[bb * 33 +  0 + jj] + xi;
        float gf = gs[bb * 33 +  8 + jj] + xf;
        float gg = gs[bb * 33 + 16 + jj] + xg;
        float go = gs[bb * 33 + 24 + jj] + xo;

        float cn = sigmoidf_(gf) * c_reg + sigmoidf_(gi) * tanhf(gg);
        float hn = sigmoidf_(go) * tanhf(cn);
        c_reg = cn;
        __stcg(h_out + bb * Hz + j0 + jj, hn);
        g_hs[((size_t)bb * Tz + t) * Hz + j0 + jj] = round_tf32(hn);

        // grid barrier: parallel flag stores + parallel polls (no serialized atomics)
        __threadfence();
        __syncthreads();
        if (tid == 0) atomicExch(&g_flags[bx], t + 1);
        if (tid < NBLK) {
            while (((volatile int*)g_flags)[tid] < t + 1) __nanosleep(32);
        }
        __syncthreads();
    }
}

// ==================== launcher ====================
extern "C" void kernel_launch(void* const* d_in, const int* in_sizes, int n_in,
                              void* d_out, int out_size) {
    const float* features = (const float*)d_in[0];
    const int*   reports  = (const int*)d_in[1];
    const float* fc_W     = (const float*)d_in[2];
    const float* fc_b     = (const float*)d_in[3];
    const float* emb      = (const float*)d_in[4];
    const float* W_ih     = (const float*)d_in[5];
    const float* W_hh     = (const float*)d_in[6];
    const float* b_ih     = (const float*)d_in[7];
    const float* b_hh     = (const float*)d_in[8];
    const float* Wv       = (const float*)d_in[9];
    const float* bv       = (const float*)d_in[10];
    float* out = (float*)d_out;

    (void)in_sizes; (void)n_in; (void)out_size;

    cudaFuncSetAttribute(lstm_persistent,
                         cudaFuncAttributeMaxDynamicSharedMemorySize, (int)SMEM_LSTM);
    cudaFuncSetAttribute(gemm_tf32_kernel<0>,
                         cudaFuncAttributeMaxDynamicSharedMemorySize, (int)GEMM_SMEM);
    cudaFuncSetAttribute(gemm_tf32_kernel<1>,
                         cudaFuncAttributeMaxDynamicSharedMemorySize, (int)GEMM_SMEM);

    // launch 0: fused prep (pool + idx + bias + flags)
    prep_kernel<<<(Bz * Fz + 255) / 256, 256>>>(features, reports, b_ih, b_hh);

    // launch 1: fused tf32 rounding (Wv, emb, W_ih)
    {
        int n = Vz * Hz + Vz * Ez + 4 * Hz * Ez;
        round_all_kernel<<<(n + 255) / 256, 256>>>(Wv, emb, W_ih);
    }

    // launch 2: init h0/c0
    init_kernel<<<128, 256>>>(fc_W, fc_b);

    // launch 3: input GEMM
    gemm_tf32_kernel<0><<<dim3(Bz * Tz / 128, 4 * Hz / 128), 256, GEMM_SMEM>>>(nullptr, nullptr);

    // launch 4: persistent LSTM (all 128 timesteps)
    lstm_persistent<<<NBLK, 256, SMEM_LSTM>>>(W_hh);

    // launch 5 (ncu-captured): projection
    gemm_tf32_kernel<1><<<dim3(Bz * Tz / 128, Vz / 128), 256, GEMM_SMEM>>>(bv, out);
}

// round 7
// speedup vs baseline: 5.4354x; 1.7261x over previous
#include <cuda_runtime.h>
#include <math.h>
#include <stdint.h>

#define Bz 32
#define Tz 128
#define Vz 16000
#define Ez 512
#define Hz 1024
#define Fz 2048
#define NBLK 128

// -------- scratch (static device globals; no runtime allocation) --------
__device__ float g_pooled[Bz * Fz];
__device__ float g_h0[Bz * Hz];
__device__ float g_h1[Bz * Hz];
__device__ float g_xW[Bz * Tz * 4 * Hz];   // input-gate preactivations
__device__ float g_hs[Bz * Tz * Hz];       // hidden states (tf32-rounded)
__device__ float g_Wv[Vz * Hz];            // Wv tf32-rounded
__device__ float g_embt[Vz * Ez];          // emb tf32-rounded
__device__ float g_Wih[4 * Hz * Ez];       // W_ih tf32-rounded
__device__ float g_bihh[4 * Hz];           // b_ih + b_hh
__device__ int   g_idx[Bz * Tz];
__device__ int   g_flags[NBLK];

__device__ __forceinline__ float sigmoidf_(float x) {
    return 1.0f / (1.0f + expf(-x));
}
__device__ __forceinline__ float round_tf32(float x) {
    uint32_t u;
    asm("cvt.rna.tf32.f32 %0, %1;" : "=r"(u) : "f"(x));
    return __uint_as_float(u);
}
__device__ __forceinline__ void cpasync16(void* dst, const void* src) {
    uint32_t d = (uint32_t)__cvta_generic_to_shared(dst);
    asm volatile("cp.async.cg.shared.global [%0], [%1], 16;" :: "r"(d), "l"(src));
}
__device__ __forceinline__ void cpasync_commit() { asm volatile("cp.async.commit_group;"); }
__device__ __forceinline__ void cpasync_wait0()  { asm volatile("cp.async.wait_group 0;"); }

__device__ __forceinline__ void mma_tf32(float* c, const uint32_t* a, const uint32_t* b) {
    asm volatile(
        "mma.sync.aligned.m16n8k8.row.col.f32.tf32.tf32.f32 "
        "{%0,%1,%2,%3}, {%4,%5,%6,%7}, {%8,%9}, {%0,%1,%2,%3};"
        : "+f"(c[0]), "+f"(c[1]), "+f"(c[2]), "+f"(c[3])
        : "r"(a[0]), "r"(a[1]), "r"(a[2]), "r"(a[3]), "r"(b[0]), "r"(b[1]));
}

// ==================== launch 0: fused small prep ====================
__global__ void prep_kernel(const float* __restrict__ features,
                            const int* __restrict__ reports,
                            const float* __restrict__ b_ih,
                            const float* __restrict__ b_hh) {
    int n = blockIdx.x * blockDim.x + threadIdx.x;   // 65536 threads
    if (n < Bz * Fz) {
        const float* p = features + (size_t)n * 49;
        float s = 0.f;
#pragma unroll
        for (int i = 0; i < 49; i++) s += p[i];
        g_pooled[n] = s * (1.0f / 49.0f);
    }
    if (n < Bz * Tz) {
        int t = n & (Tz - 1);
        g_idx[n] = (t == 0) ? 1 : reports[n - 1];    // START_IDX = 1
    }
    if (n < 4 * Hz) g_bihh[n] = b_ih[n] + b_hh[n];
    if (n < NBLK) g_flags[n] = 0;
}

// ==================== launch 1: fused tf32 rounding (float4) ====================
__global__ void round_all_kernel(const float4* __restrict__ Wv,
                                 const float4* __restrict__ emb,
                                 const float4* __restrict__ Wih) {
    int i = blockIdx.x * blockDim.x + threadIdx.x;
    const int n1 = Vz * Hz / 4, n2 = Vz * Ez / 4, n3 = 4 * Hz * Ez / 4;
    float4 v;
    float4* dst;
    const float4* src;
    if (i < n1)            { src = Wv;  dst = (float4*)g_Wv;  }
    else if ((i -= n1) < n2) { src = emb; dst = (float4*)g_embt; }
    else if ((i -= n2) < n3) { src = Wih; dst = (float4*)g_Wih; }
    else return;
    v = src[i];
    v.x = round_tf32(v.x); v.y = round_tf32(v.y);
    v.z = round_tf32(v.z); v.w = round_tf32(v.w);
    dst[i] = v;
}

// ==================== TF32 tensor-core GEMM (launches 2 and 4) ====================
// MODE 0: g_xW = g_embt[g_idx rows] @ g_Wih^T + g_bihh   (M=4096, N=4096, K=512)
// MODE 1: out  = g_hs @ g_Wv^T + bias                    (M=4096, N=16000, K=1024)
#define GROW 24
#define GEMM_SMEM (size_t)(4 * 128 * GROW * sizeof(float))

template<int MODE>
__global__ __launch_bounds__(256)
void gemm_tf32_kernel(const float* __restrict__ bias, float* __restrict__ outp)
{
    extern __shared__ float psm[];
    float* Asm = psm;
    float* Bsm = psm + 2 * 128 * GROW;

    constexpr int K = (MODE == 0) ? Ez : Hz;
    constexpr int N = (MODE == 0) ? 4 * Hz : Vz;
    const float* A  = (MODE == 0) ? g_embt : g_hs;
    const float* Bw = (MODE == 0) ? g_Wih : g_Wv;
    float* C        = (MODE == 0) ? g_xW : outp;
    const float* bias_p = (MODE == 0) ? g_bihh : bias;

    int tid = threadIdx.x;
    int m0 = blockIdx.x * 128;
    int n0 = blockIdx.y * 128;

    int wid = tid >> 5, lane = tid & 31;
    int wm = (wid >> 2) * 64;
    int wn = (wid & 3) * 32;
    int gid = lane >> 2, tig = lane & 3;

    float acc[4][4][4];
#pragma unroll
    for (int i = 0; i < 4; i++)
#pragma unroll
        for (int j = 0; j < 4; j++)
#pragma unroll
            for (int q = 0; q < 4; q++) acc[i][j][q] = 0.f;

    int ldr = tid >> 2;
    int ldc = (tid & 3) * 4;

    const float* aRow0;
    const float* aRow1;
    if (MODE == 0) {
        aRow0 = A + (size_t)g_idx[m0 + ldr] * K;
        aRow1 = A + (size_t)g_idx[m0 + ldr + 64] * K;
    } else {
        aRow0 = A + (size_t)(m0 + ldr) * K;
        aRow1 = aRow0 + (size_t)64 * K;
    }
    const float* bRow0 = Bw + (size_t)(n0 + ldr) * K;
    const float* bRow1 = bRow0 + (size_t)64 * K;

    const int NT = K / 16;

    cpasync16(&Asm[ldr * GROW + ldc],        aRow0 + ldc);
    cpasync16(&Asm[(ldr + 64) * GROW + ldc], aRow1 + ldc);
    cpasync16(&Bsm[ldr * GROW + ldc],        bRow0 + ldc);
    cpasync16(&Bsm[(ldr + 64) * GROW + ldc], bRow1 + ldc);
    cpasync_commit();

    for (int t = 0; t < NT; t++) {
        cpasync_wait0();
        __syncthreads();
        if (t + 1 < NT) {
            int nb = ((t + 1) & 1) * 128 * GROW;
            int k0 = (t + 1) * 16 + ldc;
            cpasync16(&Asm[nb + ldr * GROW + ldc],        aRow0 + k0);
            cpasync16(&Asm[nb + (ldr + 64) * GROW + ldc], aRow1 + k0);
            cpasync16(&Bsm[nb + ldr * GROW + ldc],        bRow0 + k0);
            cpasync16(&Bsm[nb + (ldr + 64) * GROW + ldc], bRow1 + k0);
            cpasync_commit();
        }
        int cb = (t & 1) * 128 * GROW;
#pragma unroll
        for (int ks = 0; ks < 2; ks++) {
            int kk = ks * 8 + 2 * tig;
            uint32_t a[4][4], b[4][2];
#pragma unroll
            for (int i = 0; i < 4; i++) {
                int r = wm + i * 16 + gid;
                float2 av0 = *(const float2*)(&Asm[cb + r * GROW + kk]);
                float2 av1 = *(const float2*)(&Asm[cb + (r + 8) * GROW + kk]);
                a[i][0] = __float_as_uint(av0.x);
                a[i][1] = __float_as_uint(av1.x);
                a[i][2] = __float_as_uint(av0.y);
                a[i][3] = __float_as_uint(av1.y);
            }
#pragma unroll
            for (int j = 0; j < 4; j++) {
                int n = wn + j * 8 + gid;
                float2 bv2 = *(const float2*)(&Bsm[cb + n * GROW + kk]);
                b[j][0] = __float_as_uint(bv2.x);
                b[j][1] = __float_as_uint(bv2.y);
            }
#pragma unroll
            for (int i = 0; i < 4; i++)
#pragma unroll
                for (int j = 0; j < 4; j++)
                    mma_tf32(acc[i][j], a[i], b[j]);
        }
        __syncthreads();
    }

#pragma unroll
    for (int j = 0; j < 4; j++) {
        int col = n0 + wn + j * 8 + tig * 2;
        float2 bvv = *(const float2*)(bias_p + col);
#pragma unroll
        for (int i = 0; i < 4; i++) {
            int r = m0 + wm + i * 16 + gid;
            float2 v0 = make_float2(acc[i][j][0] + bvv.x, acc[i][j][1] + bvv.y);
            float2 v1 = make_float2(acc[i][j][2] + bvv.x, acc[i][j][3] + bvv.y);
            *(float2*)(C + (size_t)r * N + col)       = v0;
            *(float2*)(C + (size_t)(r + 8) * N + col) = v1;
        }
    }
}

// ==================== launch 3 (ncu-captured): persistent LSTM ====================
// 128 blocks x 256 thr, 1 block/SM. Block bx owns h cols [8bx, 8bx+8) = 32 gate-rows.
// Recurrence GEMM per step via tf32 mma: M=32 batches, N=32 gate-rows, K=1024.
// W_hh slice pre-swizzled into B-fragment order (RNA tf32) at prologue.
// 8 warps split K (warp w owns k = 256c + 32w + [0,32) per chunk c); 8-way smem reduce.
// Also computes h0/c0 (init fc) in prologue, then grid-barriers.
//
// smem (floats): wfrag 32768 | hsm 2*32*264=16896 (reduce buf aliased) | gs 32*36=1152
#define HST 264
#define SMEM_LSTM (size_t)((32768 + 16896 + 1152) * sizeof(float))

__global__ __launch_bounds__(256)
void lstm_persistent(const float* __restrict__ Whh,
                     const float* __restrict__ fc_W,
                     const float* __restrict__ fc_b)
{
    extern __shared__ float sm[];
    float* wfrag = sm;                    // [32768] B-fragment-ordered W_hh slice
    float* hsm   = sm + 32768;            // [2][32][HST] h chunks
    float* red   = hsm;                   // alias after compute: [8][32][36]
    float* gs    = sm + 32768 + 16896;    // [32][36] gates / c0 buffer

    int tid = threadIdx.x;
    int bx = blockIdx.x;
    int j0 = bx * 8;
    int lane = tid & 31;
    int w = tid >> 5;
    int gid = lane >> 2, tig = lane & 3;
    int bb = tid >> 3, jj = tid & 7;

    // ---- prologue A: W_hh slice -> fragment layout, RNA tf32 ----
    // idx = ((((c*8 + w)*4 + s)*4 + nt)*64) + l*2 + r
    for (int i = tid; i < 32768; i += 256) {
        int r  = i & 1;
        int l  = (i >> 1) & 31;
        int nt = (i >> 6) & 3;
        int s  = (i >> 8) & 3;
        int ww = (i >> 10) & 7;
        int cc = i >> 13;
        int n = nt * 8 + (l >> 2);
        int grow = (n >> 3) * Hz + j0 + (n & 7);
        int k = cc * 256 + ww * 32 + s * 8 + (l & 3) + 4 * r;
        wfrag[i] = round_tf32(Whh[(size_t)grow * Hz + k]);
    }

    // ---- prologue B: init h0/c0 for this block's columns (warp-coop dots) ----
    // outputs o in [0,512): b = o&31, r = o>>5 ; r<8 -> h0 col j0+r, else c0 col j0+r-8
    for (int oo = 0; oo < 64; oo++) {
        int o = w * 64 + oo;
        int b = o & 31, r = o >> 5;
        int grow = (r < 8) ? (j0 + r) : (Hz + j0 + (r - 8));
        const float4* wp = (const float4*)(fc_W + (size_t)grow * Fz);
        const float4* pp = (const float4*)(g_pooled + (size_t)b * Fz);
        float4 s4 = make_float4(0.f, 0.f, 0.f, 0.f);
        for (int f = lane; f < Fz / 4; f += 32) {
            float4 wv = wp[f];
            float4 pv = pp[f];
            s4.x += wv.x * pv.x; s4.y += wv.y * pv.y;
            s4.z += wv.z * pv.z; s4.w += wv.w * pv.w;
        }
        float v = (s4.x + s4.y) + (s4.z + s4.w);
#pragma unroll
        for (int off = 16; off; off >>= 1) v += __shfl_xor_sync(0xffffffffu, v, off);
        if (lane == 0) {
            v += fc_b[grow];
            if (r < 8) __stcg(&g_h0[b * Hz + j0 + r], v);
            else       gs[b * 36 + (r - 8)] = v;
        }
    }
    __syncthreads();
    float c_reg = gs[bb * 36 + jj];

    // grid barrier: all h0 visible
    __threadfence();
    __syncthreads();
    if (tid == 0) atomicExch(&g_flags[bx], 1);
    if (tid < NBLK) {
        while (((volatile int*)g_flags)[tid] < 1) __nanosleep(32);
    }
    __syncthreads();

    // ---- 128 timesteps ----
    for (int t = 0; t < Tz; t++) {
        const float* h_in  = (t & 1) ? g_h1 : g_h0;
        float*       h_out = (t & 1) ? g_h0 : g_h1;

        size_t gbase = ((size_t)bb * Tz + t) * (4 * Hz);
        float xi = __ldcs(&g_xW[gbase + 0 * Hz + j0 + jj]);
        float xf = __ldcs(&g_xW[gbase + 1 * Hz + j0 + jj]);
        float xg = __ldcs(&g_xW[gbase + 2 * Hz + j0 + jj]);
        float xo = __ldcs(&g_xW[gbase + 3 * Hz + j0 + jj]);

        // stage chunk 0
#pragma unroll
        for (int it = 0; it < 8; it++) {
            int idx = tid + it * 256;
            int b = idx >> 6, k4 = idx & 63;
            cpasync16(hsm + b * HST + 4 * k4, h_in + b * Hz + 4 * k4);
        }
        cpasync_commit();

        float acc[2][4][4];
#pragma unroll
        for (int mt = 0; mt < 2; mt++)
#pragma unroll
            for (int nt = 0; nt < 4; nt++)
#pragma unroll
                for (int q = 0; q < 4; q++) acc[mt][nt][q] = 0.f;

        for (int c = 0; c < 4; c++) {
            cpasync_wait0();
            __syncthreads();
            if (c < 3) {
                float* hb = hsm + ((c + 1) & 1) * 32 * HST;
                const float* hg = h_in + (c + 1) * 256;
#pragma unroll
                for (int it = 0; it < 8; it++) {
                    int idx = tid + it * 256;
                    int b = idx >> 6, k4 = idx & 63;
                    cpasync16(hb + b * HST + 4 * k4, hg + b * Hz + 4 * k4);
                }
                cpasync_commit();
            }
            const float* hb = hsm + (c & 1) * 32 * HST;
            const float* wbase = wfrag + (c * 8 + w) * 16 * 64;
            int kw = 32 * w;
#pragma unroll
            for (int s = 0; s < 4; s++) {
                int kl = kw + 8 * s + tig;
                uint32_t a[2][4];
#pragma unroll
                for (int mt = 0; mt < 2; mt++) {
                    const float* ar = hb + (mt * 16 + gid) * HST;
                    a[mt][0] = __float_as_uint(ar[kl]);
                    a[mt][1] = __float_as_uint(ar[8 * HST + kl]);
                    a[mt][2] = __float_as_uint(ar[kl + 4]);
                    a[mt][3] = __float_as_uint(ar[8 * HST + kl + 4]);
                }
#pragma unroll
                for (int nt = 0; nt < 4; nt++) {
                    float2 bv = *(const float2*)(wbase + (s * 4 + nt) * 64 + lane * 2);
                    uint32_t b2[2] = { __float_as_uint(bv.x), __float_as_uint(bv.y) };
                    mma_tf32(acc[0][nt], a[0], b2);
                    mma_tf32(acc[1][nt], a[1], b2);
                }
            }
        }

        // ---- cross-warp reduction: red[w][row][n] (stride 36), then gs[b][n] ----
        __syncthreads();
#pragma unroll
        for (int mt = 0; mt < 2; mt++) {
#pragma unroll
            for (int nt = 0; nt < 4; nt++) {
                int row0 = mt * 16 + gid;
                int n = nt * 8 + 2 * tig;
                *(float2*)(red + (w * 32 + row0) * 36 + n) =
                    make_float2(acc[mt][nt][0], acc[mt][nt][1]);
                *(float2*)(red + (w * 32 + row0 + 8) * 36 + n) =
                    make_float2(acc[mt][nt][2], acc[mt][nt][3]);
            }
        }
        __syncthreads();
        {
            int b = tid >> 3, n4 = (tid & 7) * 4;
            float4 sum = make_float4(0.f, 0.f, 0.f, 0.f);
#pragma unroll
            for (int ww = 0; ww < 8; ww++) {
                float4 v = *(const float4*)(red + (ww * 32 + b) * 36 + n4);
                sum.x += v.x; sum.y += v.y; sum.z += v.z; sum.w += v.w;
            }
            *(float4*)(gs + b * 36 + n4) = sum;
        }
        __syncthreads();

        // ---- elementwise gate update ----
        float gi = gs[bb * 36 +  0 + jj] + xi;
        float gf = gs[bb * 36 +  8 + jj] + xf;
        float gg = gs[bb * 36 + 16 + jj] + xg;
        float go = gs[bb * 36 + 24 + jj] + xo;

        float cn = sigmoidf_(gf) * c_reg + sigmoidf_(gi) * tanhf(gg);
        float hn = sigmoidf_(go) * tanhf(cn);
        c_reg = cn;
        float hr = round_tf32(hn);
        __stcg(h_out + bb * Hz + j0 + jj, hr);
        g_hs[((size_t)bb * Tz + t) * Hz + j0 + jj] = hr;

        // ---- grid barrier ----
        __threadfence();
        __syncthreads();
        if (tid == 0) atomicExch(&g_flags[bx], t + 2);
        if (tid < NBLK) {
            while (((volatile int*)g_flags)[tid] < t + 2) __nanosleep(32);
        }
        __syncthreads();
    }
}

// ==================== launcher ====================
extern "C" void kernel_launch(void* const* d_in, const int* in_sizes, int n_in,
                              void* d_out, int out_size) {
    const float* features = (const float*)d_in[0];
    const int*   reports  = (const int*)d_in[1];
    const float* fc_W     = (const float*)d_in[2];
    const float* fc_b     = (const float*)d_in[3];
    const float* emb      = (const float*)d_in[4];
    const float* W_ih     = (const float*)d_in[5];
    const float* W_hh     = (const float*)d_in[6];
    const float* b_ih     = (const float*)d_in[7];
    const float* b_hh     = (const float*)d_in[8];
    const float* Wv       = (const float*)d_in[9];
    const float* bv       = (const float*)d_in[10];
    float* out = (float*)d_out;

    (void)in_sizes; (void)n_in; (void)out_size;

    cudaFuncSetAttribute(lstm_persistent,
                         cudaFuncAttributeMaxDynamicSharedMemorySize, (int)SMEM_LSTM);
    cudaFuncSetAttribute(gemm_tf32_kernel<0>,
                         cudaFuncAttributeMaxDynamicSharedMemorySize, (int)GEMM_SMEM);
    cudaFuncSetAttribute(gemm_tf32_kernel<1>,
                         cudaFuncAttributeMaxDynamicSharedMemorySize, (int)GEMM_SMEM);

    // launch 0: fused prep (pool + idx + bias + flags)
    prep_kernel<<<(Bz * Fz + 255) / 256, 256>>>(features, reports, b_ih, b_hh);

    // launch 1: fused tf32 rounding (Wv, emb, W_ih), float4
    {
        int n = (Vz * Hz + Vz * Ez + 4 * Hz * Ez) / 4;
        round_all_kernel<<<(n + 255) / 256, 256>>>((const float4*)Wv,
                                                   (const float4*)emb,
                                                   (const float4*)W_ih);
    }

    // launch 2: input GEMM  xW = emb[idx] @ W_ih^T + (b_ih + b_hh)
    gemm_tf32_kernel<0><<<dim3(Bz * Tz / 128, 4 * Hz / 128), 256, GEMM_SMEM>>>(nullptr, nullptr);

    // launch 3 (ncu-captured): persistent LSTM (init + 128 timesteps)
    lstm_persistent<<<NBLK, 256, SMEM_LSTM>>>(W_hh, fc_W, fc_b);

    // launch 4: projection  out = hs @ Wv^T + bv
    gemm_tf32_kernel<1><<<dim3(Bz * Tz / 128, Vz / 128), 256, GEMM_SMEM>>>(bv, out);
}